// round 4
// baseline (speedup 1.0000x reference)
#include <cuda_runtime.h>

#define BB   4
#define SQL  4096
#define SKVL 4096
#define DINL 256
#define DKL  256

// Scratch for projected Q, K, V (static __device__ arrays — allowed; no runtime alloc)
__device__ float g_Q[(size_t)BB * SQL  * DKL];
__device__ float g_K[(size_t)BB * SKVL * DKL];
__device__ float g_V[(size_t)BB * SKVL * DKL];

// ---------------------------------------------------------------------------
// Projection GEMM: C[M][256] = A[M][256] @ W[256][256] + bias
// BM=64, BN=64, BK=32, 256 threads, 4x4 register tile per thread.
// ---------------------------------------------------------------------------
__global__ __launch_bounds__(256) void proj_gemm(const float* __restrict__ A,
                                                 const float* __restrict__ W,
                                                 const float* __restrict__ bias,
                                                 float* __restrict__ C) {
    __shared__ float sA[64][36];   // pitch 36 floats (144B, 16B-aligned rows)
    __shared__ float sW[32][68];   // pitch 68 floats (272B, 16B-aligned rows)
    const int m0 = blockIdx.x * 64;
    const int n0 = blockIdx.y * 64;
    const int tid = threadIdx.x;
    const int tx = tid & 15, ty = tid >> 4;

    float acc[4][4] = {};

    for (int k0 = 0; k0 < DINL; k0 += 32) {
        __syncthreads();
#pragma unroll
        for (int r = 0; r < 2; r++) {
            int s = tid + r * 256;
            int row = s >> 3, seg = s & 7;              // 64 rows x 8 float4
            *(float4*)&sA[row][seg * 4] =
                *(const float4*)(A + (size_t)(m0 + row) * DINL + k0 + seg * 4);
        }
#pragma unroll
        for (int r = 0; r < 2; r++) {
            int s = tid + r * 256;
            int row = s >> 4, seg = s & 15;             // 32 rows x 16 float4
            *(float4*)&sW[row][seg * 4] =
                *(const float4*)(W + (size_t)(k0 + row) * DKL + n0 + seg * 4);
        }
        __syncthreads();
#pragma unroll
        for (int kk = 0; kk < 32; kk += 4) {
            float4 w0 = *(const float4*)&sW[kk + 0][tx * 4];
            float4 w1 = *(const float4*)&sW[kk + 1][tx * 4];
            float4 w2 = *(const float4*)&sW[kk + 2][tx * 4];
            float4 w3 = *(const float4*)&sW[kk + 3][tx * 4];
#pragma unroll
            for (int i = 0; i < 4; i++) {
                float4 a = *(const float4*)&sA[ty * 4 + i][kk];
                acc[i][0] += a.x * w0.x + a.y * w1.x + a.z * w2.x + a.w * w3.x;
                acc[i][1] += a.x * w0.y + a.y * w1.y + a.z * w2.y + a.w * w3.y;
                acc[i][2] += a.x * w0.z + a.y * w1.z + a.z * w2.z + a.w * w3.z;
                acc[i][3] += a.x * w0.w + a.y * w1.w + a.z * w2.w + a.w * w3.w;
            }
        }
    }
    float4 bv = *(const float4*)(bias + n0 + tx * 4);
#pragma unroll
    for (int i = 0; i < 4; i++) {
        float4 o = make_float4(acc[i][0] + bv.x, acc[i][1] + bv.y,
                               acc[i][2] + bv.z, acc[i][3] + bv.w);
        *(float4*)(C + (size_t)(m0 + ty * 4 + i) * DKL + n0 + tx * 4) = o;
    }
}

// ---------------------------------------------------------------------------
// Flash attention, fp32. BM=64 q-rows per block, BN=64 kv per tile.
// Q tile resident in smem; K streamed in 64x32 chunks; V in 64x64 chunks,
// both with register prefetch. Online softmax; per-thread row state
// (row ownership identical in S and PV phases: rows = ty*4 + i).
// Smem: Q 64x260 + K 64x36 + V 64x68 + PT 64x68 = 110592 B -> 2 blocks/SM,
// grid of 256 blocks = one full wave on 148 SMs.
// ---------------------------------------------------------------------------
#define QP 260
#define KP 36
#define VP 68
#define PP 68

__global__ __launch_bounds__(256, 2) void attn_kernel(float* __restrict__ out) {
    extern __shared__ float sm[];
    float* sQ  = sm;                 // 64 * QP
    float* sK  = sQ + 64 * QP;       // 64 * KP
    float* sV  = sK + 64 * KP;       // 64 * VP
    float* sPT = sV + 64 * VP;       // 64 * PP   (P transposed: [kv][qrow])

    const int b  = blockIdx.x >> 6;
    const int q0 = (blockIdx.x & 63) * 64;
    const float* Qg = g_Q + ((size_t)b * SQL + q0) * DKL;
    const float* Kg = g_K + (size_t)b * SKVL * DKL;
    const float* Vg = g_V + (size_t)b * SKVL * DKL;

    const int tid = threadIdx.x;
    const int tx = tid & 15, ty = tid >> 4;

    // Load Q tile (64 x 256) into smem
    for (int s = tid; s < 64 * 64; s += 256) {
        int row = s >> 6, seg = s & 63;
        *(float4*)&sQ[row * QP + seg * 4] =
            *(const float4*)(Qg + (size_t)row * DKL + seg * 4);
    }

    float O[4][16];
#pragma unroll
    for (int i = 0; i < 4; i++)
#pragma unroll
        for (int c = 0; c < 16; c++) O[i][c] = 0.f;
    float m_i[4] = {-1e30f, -1e30f, -1e30f, -1e30f};
    float l_i[4] = {0.f, 0.f, 0.f, 0.f};

    for (int kv = 0; kv < SKVL; kv += 64) {
        const float* Kt = Kg + (size_t)kv * DKL;
        const float* Vt = Vg + (size_t)kv * DKL;

        // ---- S = Q @ K^T (this tile), streamed over d in 32-wide chunks ----
        float S[4][4] = {};
        float4 kreg[2];
#pragma unroll
        for (int r = 0; r < 2; r++) {   // prefetch K chunk 0
            int s = tid + r * 256;
            kreg[r] = *(const float4*)(Kt + (size_t)(s >> 3) * DKL + (s & 7) * 4);
        }
        for (int dc = 0; dc < 8; dc++) {
            __syncthreads();
#pragma unroll
            for (int r = 0; r < 2; r++) {
                int s = tid + r * 256;
                *(float4*)&sK[(s >> 3) * KP + (s & 7) * 4] = kreg[r];
            }
            __syncthreads();
            if (dc < 7) {
#pragma unroll
                for (int r = 0; r < 2; r++) {
                    int s = tid + r * 256;
                    kreg[r] = *(const float4*)(Kt + (size_t)(s >> 3) * DKL +
                                               (dc + 1) * 32 + (s & 7) * 4);
                }
            }
            const int dbase = dc * 32;
#pragma unroll
            for (int d = 0; d < 32; d += 4) {
                // cols = tx + 16*jj (stride-16 mapping -> conflict-free LDS.128)
                float4 k0 = *(const float4*)&sK[(tx     ) * KP + d];
                float4 k1 = *(const float4*)&sK[(tx + 16) * KP + d];
                float4 k2 = *(const float4*)&sK[(tx + 32) * KP + d];
                float4 k3 = *(const float4*)&sK[(tx + 48) * KP + d];
#pragma unroll
                for (int i = 0; i < 4; i++) {
                    float4 q = *(const float4*)&sQ[(ty * 4 + i) * QP + dbase + d];
                    S[i][0] += q.x * k0.x + q.y * k0.y + q.z * k0.z + q.w * k0.w;
                    S[i][1] += q.x * k1.x + q.y * k1.y + q.z * k1.z + q.w * k1.w;
                    S[i][2] += q.x * k2.x + q.y * k2.y + q.z * k2.z + q.w * k2.w;
                    S[i][3] += q.x * k3.x + q.y * k3.y + q.z * k3.z + q.w * k3.w;
                }
            }
        }

        // ---- online softmax (row groups of 16 lanes; butterfly over tx) ----
        float p[4][4];
        float osc[4];
#pragma unroll
        for (int i = 0; i < 4; i++) {
            float mloc = -1e30f;
#pragma unroll
            for (int jj = 0; jj < 4; jj++) {
                S[i][jj] *= 0.0625f;                       // 1/sqrt(256)
                mloc = fmaxf(mloc, S[i][jj]);
            }
#pragma unroll
            for (int off = 8; off > 0; off >>= 1)
                mloc = fmaxf(mloc, __shfl_xor_sync(0xffffffffu, mloc, off));
            float mn = fmaxf(m_i[i], mloc);
            float sc = __expf(m_i[i] - mn);
            float ts = 0.f;
#pragma unroll
            for (int jj = 0; jj < 4; jj++) {
                p[i][jj] = __expf(S[i][jj] - mn);
                ts += p[i][jj];
            }
#pragma unroll
            for (int off = 8; off > 0; off >>= 1)
                ts += __shfl_xor_sync(0xffffffffu, ts, off);
            l_i[i] = l_i[i] * sc + ts;
            m_i[i] = mn;
            osc[i] = sc;
        }
        // store P transposed: PT[col][qrow], STS.128 per jj, conflict-free
#pragma unroll
        for (int jj = 0; jj < 4; jj++) {
            float4 v = make_float4(p[0][jj], p[1][jj], p[2][jj], p[3][jj]);
            *(float4*)&sPT[(tx + 16 * jj) * PP + ty * 4] = v;
        }
        // rescale running O
#pragma unroll
        for (int i = 0; i < 4; i++)
#pragma unroll
            for (int c = 0; c < 16; c++) O[i][c] *= osc[i];

        // ---- O += P @ V, V streamed in 64x64 column chunks ----
        float4 vreg[4];
#pragma unroll
        for (int r = 0; r < 4; r++) {   // prefetch V chunk 0
            int s = tid + r * 256;
            vreg[r] = *(const float4*)(Vt + (size_t)(s >> 4) * DKL + (s & 15) * 4);
        }
        for (int ch = 0; ch < 4; ch++) {
            __syncthreads();   // also guards sPT visibility on first chunk
#pragma unroll
            for (int r = 0; r < 4; r++) {
                int s = tid + r * 256;
                *(float4*)&sV[(s >> 4) * VP + (s & 15) * 4] = vreg[r];
            }
            __syncthreads();
            if (ch < 3) {
#pragma unroll
                for (int r = 0; r < 4; r++) {
                    int s = tid + r * 256;
                    vreg[r] = *(const float4*)(Vt + (size_t)(s >> 4) * DKL +
                                               (ch + 1) * 64 + (s & 15) * 4);
                }
            }
            const int c4 = ch * 4;
#pragma unroll 16
            for (int j = 0; j < 64; j++) {
                float4 pv = *(const float4*)&sPT[j * PP + ty * 4];  // broadcast
                float4 vv = *(const float4*)&sV[j * VP + tx * 4];   // contiguous
                O[0][c4+0] += pv.x*vv.x; O[0][c4+1] += pv.x*vv.y; O[0][c4+2] += pv.x*vv.z; O[0][c4+3] += pv.x*vv.w;
                O[1][c4+0] += pv.y*vv.x; O[1][c4+1] += pv.y*vv.y; O[1][c4+2] += pv.y*vv.z; O[1][c4+3] += pv.y*vv.w;
                O[2][c4+0] += pv.z*vv.x; O[2][c4+1] += pv.z*vv.y; O[2][c4+2] += pv.z*vv.z; O[2][c4+3] += pv.z*vv.w;
                O[3][c4+0] += pv.w*vv.x; O[3][c4+1] += pv.w*vv.y; O[3][c4+2] += pv.w*vv.z; O[3][c4+3] += pv.w*vv.w;
            }
        }
    }

    // ---- epilogue: divide by row sums, write out ----
#pragma unroll
    for (int i = 0; i < 4; i++) {
        float inv = 1.0f / l_i[i];
        float* orow = out + ((size_t)b * SQL + q0 + ty * 4 + i) * DKL;
#pragma unroll
        for (int ch = 0; ch < 4; ch++) {
            float4 o = make_float4(O[i][ch*4+0] * inv, O[i][ch*4+1] * inv,
                                   O[i][ch*4+2] * inv, O[i][ch*4+3] * inv);
            *(float4*)(orow + ch * 64 + tx * 4) = o;
        }
    }
}

// ---------------------------------------------------------------------------
extern "C" void kernel_launch(void* const* d_in, const int* in_sizes, int n_in,
                              void* d_out, int out_size) {
    (void)in_sizes; (void)n_in; (void)out_size;
    const float* conv_local  = (const float*)d_in[0];
    const float* conv_global = (const float*)d_in[1];
    const float* Wk = (const float*)d_in[2];
    const float* bk = (const float*)d_in[3];
    const float* Wq = (const float*)d_in[4];
    const float* bq = (const float*)d_in[5];
    const float* Wv = (const float*)d_in[6];
    const float* bv = (const float*)d_in[7];
    float* out = (float*)d_out;

    void *qp, *kp, *vp;
    cudaGetSymbolAddress(&qp, g_Q);
    cudaGetSymbolAddress(&kp, g_K);
    cudaGetSymbolAddress(&vp, g_V);

    dim3 ggrid((BB * SKVL) / 64, DKL / 64);
    proj_gemm<<<ggrid, 256>>>(conv_local,  Wk, bk, (float*)kp);
    proj_gemm<<<ggrid, 256>>>(conv_local,  Wv, bv, (float*)vp);
    proj_gemm<<<ggrid, 256>>>(conv_global, Wq, bq, (float*)qp);

    const int smem = (64 * QP + 64 * KP + 64 * VP + 64 * PP) * (int)sizeof(float);
    cudaFuncSetAttribute(attn_kernel, cudaFuncAttributeMaxDynamicSharedMemorySize, smem);
    attn_kernel<<<BB * (SQL / 64), 256, smem>>>(out);
}